// round 1
// baseline (speedup 1.0000x reference)
#include <cuda_runtime.h>

#define B_      256
#define SEQ_    128
#define HID_    1024
#define NB_     256
#define NL_     3
#define G_      4              // k-values per CTA in pass 1
#define KG_     (NB_/G_)       // 64 k-groups
#define CHUNKS_ 8              // b-chunks (split softmax)
#define BPC_    (B_/CHUNKS_)   // 32 b per chunk
#define RHS_    32             // h-splits for R@H partial kernel

// Scratch (static device allocations only — no cudaMalloc allowed)
__device__ float g_part_u[NB_][CHUNKS_][HID_];   // 8 MB
__device__ float g_part_m[NB_][CHUNKS_];
__device__ float g_part_z[NB_][CHUNKS_];
__device__ float g_u[NB_][HID_];                 // 1 MB
__device__ float g_RHp[RHS_][NL_][HID_];         // partials of R_w @ H_w
__device__ float g_RH[NL_][HID_];                // R_w @ H_w  (3 x 1024)
__device__ float g_act[B_][HID_];                // slow-path activations
__device__ int   g_flag;                         // 1 iff alpha == 1 everywhere

// ---------------------------------------------------------------------------
// K1: one-pass online-softmax weighted accumulation over a b-chunk.
// Grid (KG_, CHUNKS_), 256 threads. Thread t owns h = 4t..4t+3 (float4).
// Each CTA handles G_=4 consecutive k values so the x float4 is reused 4x.
// ---------------------------------------------------------------------------
__global__ __launch_bounds__(256) void k1_partials(
    const float* __restrict__ ee, const float* __restrict__ S)
{
    const int kg = blockIdx.x;
    const int c  = blockIdx.y;
    const int t  = threadIdx.x;
    const int h4 = t * 4;
    const int b0 = c * BPC_;
    const int kbase = kg * G_;

    __shared__ float4 red[8];
    __shared__ float4 bcast;

    float4 acc[G_];
    float m[G_], z[G_];
#pragma unroll
    for (int g = 0; g < G_; g++) {
        acc[g] = make_float4(0.f, 0.f, 0.f, 0.f);
        m[g] = -3.0e38f;
        z[g] = 0.f;
    }

    // prime the pipeline
    float4 xv = *(const float4*)(ee + (size_t)b0 * SEQ_ * HID_ + h4);
    float4 sv[G_];
#pragma unroll
    for (int g = 0; g < G_; g++)
        sv[g] = *(const float4*)(S + ((size_t)b0 * NB_ + kbase + g) * HID_ + h4);

    for (int bi = 0; bi < BPC_; bi++) {
        // prefetch next b while we reduce the current one
        float4 xv_n = xv;
        float4 sv_n[G_];
#pragma unroll
        for (int g = 0; g < G_; g++) sv_n[g] = sv[g];
        if (bi + 1 < BPC_) {
            const int bn = b0 + bi + 1;
            xv_n = *(const float4*)(ee + (size_t)bn * SEQ_ * HID_ + h4);
#pragma unroll
            for (int g = 0; g < G_; g++)
                sv_n[g] = *(const float4*)(S + ((size_t)bn * NB_ + kbase + g) * HID_ + h4);
        }

        // 4 partial dots (one per k) packed in a float4
        float4 d;
        d.x = xv.x*sv[0].x + xv.y*sv[0].y + xv.z*sv[0].z + xv.w*sv[0].w;
        d.y = xv.x*sv[1].x + xv.y*sv[1].y + xv.z*sv[1].z + xv.w*sv[1].w;
        d.z = xv.x*sv[2].x + xv.y*sv[2].y + xv.z*sv[2].z + xv.w*sv[2].w;
        d.w = xv.x*sv[3].x + xv.y*sv[3].y + xv.z*sv[3].z + xv.w*sv[3].w;
#pragma unroll
        for (int off = 16; off > 0; off >>= 1) {
            d.x += __shfl_xor_sync(0xffffffffu, d.x, off);
            d.y += __shfl_xor_sync(0xffffffffu, d.y, off);
            d.z += __shfl_xor_sync(0xffffffffu, d.z, off);
            d.w += __shfl_xor_sync(0xffffffffu, d.w, off);
        }
        if ((t & 31) == 0) red[t >> 5] = d;
        __syncthreads();
        if (t == 0) {
            float4 s = red[0];
#pragma unroll
            for (int w2 = 1; w2 < 8; w2++) {
                float4 r = red[w2];
                s.x += r.x; s.y += r.y; s.z += r.z; s.w += r.w;
            }
            bcast = s;
        }
        __syncthreads();
        const float4 sc = bcast;
        const float scv[4] = { sc.x, sc.y, sc.z, sc.w };

#pragma unroll
        for (int g = 0; g < G_; g++) {
            const float s_ = scv[g];
            if (s_ > m[g]) {           // block-uniform branch
                const float cf = __expf(m[g] - s_);   // first iter: exp(-huge)=0
                z[g] = z[g] * cf + 1.f;
                acc[g].x = acc[g].x * cf + sv[g].x;
                acc[g].y = acc[g].y * cf + sv[g].y;
                acc[g].z = acc[g].z * cf + sv[g].z;
                acc[g].w = acc[g].w * cf + sv[g].w;
                m[g] = s_;
            } else {
                const float w = __expf(s_ - m[g]);
                z[g] += w;
                acc[g].x += w * sv[g].x;
                acc[g].y += w * sv[g].y;
                acc[g].z += w * sv[g].z;
                acc[g].w += w * sv[g].w;
            }
        }
        xv = xv_n;
#pragma unroll
        for (int g = 0; g < G_; g++) sv[g] = sv_n[g];
    }

#pragma unroll
    for (int g = 0; g < G_; g++) {
        const int k = kbase + g;
        *(float4*)&g_part_u[k][c][h4] = acc[g];
        if (t == 0) { g_part_m[k][c] = m[g]; g_part_z[k][c] = z[g]; }
    }
}

// ---------------------------------------------------------------------------
// K2: combine the 8 split-softmax partials per k into u[k][:].
// Block 0 also computes the alpha==1 flag.
// ---------------------------------------------------------------------------
__global__ __launch_bounds__(256) void k2_combine(const float* __restrict__ alpha)
{
    const int k = blockIdx.x;
    const int t = threadIdx.x;
    const int h4 = t * 4;

    if (k == 0) {
        int ok = 1;
#pragma unroll
        for (int r = 0; r < 4; r++) ok &= (alpha[h4 + r] == 1.0f);
        ok = __syncthreads_and(ok);
        if (t == 0) g_flag = ok;
    }

    float m = -3.0e38f;
#pragma unroll
    for (int c = 0; c < CHUNKS_; c++) m = fmaxf(m, g_part_m[k][c]);
    float Z = 0.f, w[CHUNKS_];
#pragma unroll
    for (int c = 0; c < CHUNKS_; c++) {
        w[c] = __expf(g_part_m[k][c] - m);
        Z += g_part_z[k][c] * w[c];
    }
    const float inv = 1.f / Z;
    float4 s = make_float4(0.f, 0.f, 0.f, 0.f);
#pragma unroll
    for (int c = 0; c < CHUNKS_; c++) {
        const float4 p = *(const float4*)&g_part_u[k][c][h4];
        const float ww = w[c] * inv;
        s.x += ww * p.x; s.y += ww * p.y; s.z += ww * p.z; s.w += ww * p.w;
    }
    *(float4*)&g_u[k][h4] = s;
}

// ---------------------------------------------------------------------------
// R@H stage 1: partials of RH[l][j] = sum_h R[l,h] * H[h,j] over an h-split.
// Grid RHS_ blocks, 256 threads, thread t owns j = 4t..4t+3.
// ---------------------------------------------------------------------------
__global__ __launch_bounds__(256) void k_rh1(
    const float* __restrict__ Rw, const float* __restrict__ Hw)
{
    const int hs = blockIdx.x;
    const int j4 = threadIdx.x * 4;
    float4 a0 = make_float4(0,0,0,0), a1 = a0, a2 = a0;
    const int hstep = HID_ / RHS_;   // 32
#pragma unroll 4
    for (int hh = 0; hh < hstep; hh++) {
        const int h = hs * hstep + hh;
        const float4 hv = *(const float4*)(Hw + (size_t)h * HID_ + j4);
        const float r0 = Rw[0 * HID_ + h];
        const float r1 = Rw[1 * HID_ + h];
        const float r2 = Rw[2 * HID_ + h];
        a0.x += r0*hv.x; a0.y += r0*hv.y; a0.z += r0*hv.z; a0.w += r0*hv.w;
        a1.x += r1*hv.x; a1.y += r1*hv.y; a1.z += r1*hv.z; a1.w += r1*hv.w;
        a2.x += r2*hv.x; a2.y += r2*hv.y; a2.z += r2*hv.z; a2.w += r2*hv.w;
    }
    *(float4*)&g_RHp[hs][0][j4] = a0;
    *(float4*)&g_RHp[hs][1][j4] = a1;
    *(float4*)&g_RHp[hs][2][j4] = a2;
}

// R@H stage 2: reduce the RHS_ partials. 3072 outputs.
__global__ __launch_bounds__(256) void k_rh2()
{
    const int idx = blockIdx.x * 256 + threadIdx.x;   // 0..3071
    const int l = idx >> 10;
    const int j = idx & 1023;
    float s = 0.f;
#pragma unroll
    for (int hs = 0; hs < RHS_; hs++) s += g_RHp[hs][l][j];
    g_RH[l][j] = s;
}

// ---------------------------------------------------------------------------
// Fast path (alpha == 1 so PReLU is identity):
//   out[i][l] = x[i]·R_w[l] + u[i]·RH[l]
// One warp per output (768 warps).
// ---------------------------------------------------------------------------
__global__ __launch_bounds__(256) void k_fast(
    const float* __restrict__ ee, const float* __restrict__ Rw,
    float* __restrict__ out)
{
    if (!g_flag) return;
    const int w = (blockIdx.x * 256 + threadIdx.x) >> 5;
    if (w >= B_ * NL_) return;
    const int i = w / NL_;
    const int l = w % NL_;
    const int lane = threadIdx.x & 31;
    const float* xr = ee + (size_t)i * SEQ_ * HID_;
    float s = 0.f;
#pragma unroll 8
    for (int j = lane; j < HID_; j += 32)
        s += xr[j] * Rw[l * HID_ + j] + g_u[i][j] * g_RH[l][j];
#pragma unroll
    for (int off = 16; off > 0; off >>= 1)
        s += __shfl_xor_sync(0xffffffffu, s, off);
    if (lane == 0) out[i * NL_ + l] = s;
}

// ---------------------------------------------------------------------------
// Slow path (general alpha): v = x + u@H^T, act = PReLU(v)  -> g_act.
// Tiled 32x32 SGEMM-NT. Early-exits when flag==1.
// ---------------------------------------------------------------------------
__global__ __launch_bounds__(256) void k3_full(
    const float* __restrict__ ee, const float* __restrict__ Hw,
    const float* __restrict__ alpha)
{
    if (g_flag) return;
    __shared__ float Us[32][33];
    __shared__ float Hs[32][33];
    const int t  = threadIdx.x;
    const int tx = t & 15, ty = t >> 4;
    const int i0 = blockIdx.x * 32, h0 = blockIdx.y * 32;
    const int lr = t >> 3;           // 0..31
    const int lc = (t & 7) * 4;      // 0,4,..28
    float acc00 = 0.f, acc01 = 0.f, acc10 = 0.f, acc11 = 0.f;

    for (int kk = 0; kk < HID_; kk += 32) {
        const float4 uu = *(const float4*)&g_u[i0 + lr][kk + lc];
        const float4 hh = *(const float4*)(Hw + (size_t)(h0 + lr) * HID_ + kk + lc);
        Us[lr][lc] = uu.x; Us[lr][lc+1] = uu.y; Us[lr][lc+2] = uu.z; Us[lr][lc+3] = uu.w;
        Hs[lr][lc] = hh.x; Hs[lr][lc+1] = hh.y; Hs[lr][lc+2] = hh.z; Hs[lr][lc+3] = hh.w;
        __syncthreads();
#pragma unroll
        for (int j = 0; j < 32; j++) {
            const float a0 = Us[ty*2][j],   a1 = Us[ty*2+1][j];
            const float b0 = Hs[tx*2][j],   b1 = Hs[tx*2+1][j];
            acc00 += a0*b0; acc01 += a0*b1; acc10 += a1*b0; acc11 += a1*b1;
        }
        __syncthreads();
    }
    const float accs[2][2] = { {acc00, acc01}, {acc10, acc11} };
#pragma unroll
    for (int ii = 0; ii < 2; ii++)
#pragma unroll
        for (int jj = 0; jj < 2; jj++) {
            const int i = i0 + ty*2 + ii;
            const int h = h0 + tx*2 + jj;
            const float v = accs[ii][jj] + ee[(size_t)i * SEQ_ * HID_ + h];
            g_act[i][h] = (v >= 0.f) ? v : alpha[h] * v;
        }
}

// Slow path final: out = act @ R_w^T. One warp per output.
__global__ __launch_bounds__(256) void k4_full(
    const float* __restrict__ Rw, float* __restrict__ out)
{
    if (g_flag) return;
    const int w = (blockIdx.x * 256 + threadIdx.x) >> 5;
    if (w >= B_ * NL_) return;
    const int i = w / NL_;
    const int l = w % NL_;
    const int lane = threadIdx.x & 31;
    float s = 0.f;
#pragma unroll 8
    for (int j = lane; j < HID_; j += 32)
        s += g_act[i][j] * Rw[l * HID_ + j];
#pragma unroll
    for (int off = 16; off > 0; off >>= 1)
        s += __shfl_xor_sync(0xffffffffu, s, off);
    if (lane == 0) out[i * NL_ + l] = s;
}

// ---------------------------------------------------------------------------
extern "C" void kernel_launch(void* const* d_in, const int* in_sizes, int n_in,
                              void* d_out, int out_size)
{
    const float* ee = (const float*)d_in[0];   // (256,128,1024)
    const float* S  = (const float*)d_in[1];   // (256, 256*1024)
    const float* Hw = (const float*)d_in[2];   // (1024,1024)
    const float* Rw = (const float*)d_in[3];   // (3,1024)
    const float* al = (const float*)d_in[4];   // (1024,)
    float* out = (float*)d_out;                // (256,3)

    k1_partials<<<dim3(KG_, CHUNKS_), 256>>>(ee, S);
    k2_combine<<<NB_, 256>>>(al);
    k_rh1<<<RHS_, 256>>>(Rw, Hw);
    k_rh2<<<(NL_ * HID_) / 256, 256>>>();
    k3_full<<<dim3(B_ / 32, HID_ / 32), 256>>>(ee, Hw, al);
    k4_full<<<(B_ * NL_ * 32) / 256, 256>>>(Rw, out);
    k_fast<<<(B_ * NL_ * 32) / 256, 256>>>(ee, Rw, out);
}